// round 5
// baseline (speedup 1.0000x reference)
#include <cuda_runtime.h>

// Problem constants
#define TT    1200              // time length
#define XPAD  1216              // padded row: 8-zero halo each side
#define NF    10                // conv filters
#define KK    17                // conv kernel width (pad 8 both sides)
#define WSTR  18                // padded per-filter weight stride (u64), 16B-aligned
#define NSTR  240               // 5-wide output strips per row (1200/5)
#define NTP   76                // pooled length
#define NTPG  19                // groups of 4 pooled outputs (76/4)
#define FEAT  (NF*NTP)          // 760
#define NPAIR 4                 // row-pairs per block
#define THREADS 256

typedef unsigned long long u64;

__device__ __forceinline__ u64 pack2(float lo, float hi) {
    u64 r;
    asm("mov.b64 %0, {%1, %2};" : "=l"(r) : "f"(lo), "f"(hi));
    return r;
}
__device__ __forceinline__ void unpack2(u64 v, float& lo, float& hi) {
    asm("mov.b64 {%0, %1}, %2;" : "=f"(lo), "=f"(hi) : "l"(v));
}
__device__ __forceinline__ u64 ffma2(u64 a, u64 b, u64 c) {
    u64 d;
    asm("fma.rn.f32x2 %0, %1, %2, %3;" : "=l"(d) : "l"(a), "l"(b), "l"(c));
    return d;
}
__device__ __forceinline__ u64 add2(u64 a, u64 b) {
    u64 d;
    asm("add.rn.f32x2 %0, %1, %2;" : "=l"(d) : "l"(a), "l"(b));
    return d;
}
__device__ __forceinline__ u64 sub2(u64 a, u64 b) {
    u64 d;
    asm("sub.rn.f32x2 %0, %1, %2;" : "=l"(d) : "l"(a), "l"(b));
    return d;
}
__device__ __forceinline__ void cp16(void* smem_dst, const void* gmem_src) {
    unsigned s;
    asm("{ .reg .u64 t; cvta.to.shared.u64 t, %0; cvt.u32.u64 %1, t; }"
        : : "l"(smem_dst), "r"(s));
    asm volatile("cp.async.ca.shared.global [%0], [%1], 16;"
                 :: "r"((unsigned)__cvta_generic_to_shared(smem_dst)), "l"(gmem_src)
                 : "memory");
}
__device__ __forceinline__ void cp_commit() {
    asm volatile("cp.async.commit_group;" ::: "memory");
}
__device__ __forceinline__ void cp_wait1() {
    asm volatile("cp.async.wait_group 1;" ::: "memory");
}
__device__ __forceinline__ void cp_wait0() {
    asm volatile("cp.async.wait_group 0;" ::: "memory");
}

__global__ __launch_bounds__(THREADS) void scorer_kernel(
    const float* __restrict__ x,       // (B,1,M,T) rows of 1200
    const float* __restrict__ conv_w,  // (NF,1,KK)
    const float* __restrict__ conv_b,  // (NF)
    const float* __restrict__ lin_w,   // (M, FEAT)
    const float* __restrict__ lin_b,   // (M)
    float* __restrict__ out)           // (B,M,1)
{
    __shared__ __align__(16) float s_x[2][2][XPAD];  // [buf][row][t], halo 8 each side
    __shared__ u64   s_w2[NF * WSTR];  // {w,w}, padded stride 18 (16B-aligned/filter)
    __shared__ u64   s_b2[NF];         // {b,b}
    __shared__ u64   s_S2[NF * NSTR];  // packed {S_row0, S_row1} strip sums
    __shared__ float s_out[2];

    const int tid = threadIdx.x;

    // ---- One-time staging: packed padded weights, halo zeros ----
    for (int i = tid; i < NF * WSTR; i += THREADS) {
        int f = i / WSTR, k = i - f * WSTR;
        float w = (k < KK) ? conv_w[f * KK + k] : 0.f;
        s_w2[i] = pack2(w, w);
    }
    if (tid < NF) { float b = conv_b[tid]; s_b2[tid] = pack2(b, b); }
    if (tid < 64) {
        int buf = tid >> 5, rr = (tid >> 4) & 1, j = tid & 15;
        if (j < 8) s_x[buf][rr][j] = 0.f;
        else       s_x[buf][rr][TT + j] = 0.f;
    }

    // ---- Prefetch helper: pair -> buffer (2 rows x 300 float4) ----
    const long long pair0 = (long long)blockIdx.x * NPAIR;
    #define PREFETCH(P, BUF) do {                                              \
        const float* base = x + (size_t)((pair0 + (P)) * 2) * TT;              \
        for (int c = tid; c < 600; c += THREADS) {                             \
            int rr = c / 300, cc = c - rr * 300;                               \
            cp16(&s_x[BUF][rr][8 + cc * 4], base + (size_t)rr * TT + cc * 4);  \
        }                                                                      \
        cp_commit();                                                           \
    } while (0)

    PREFETCH(0, 0);
    PREFETCH(1, 1);

    for (int p = 0; p < NPAIR; ++p) {
        const int buf  = p & 1;
        const long long row0 = (pair0 + p) * 2;
        const int m0   = (int)(row0 & 63);

        if (p < NPAIR - 1) cp_wait1(); else cp_wait0();
        if (tid < 2) s_out[tid] = 0.f;
        __syncthreads();   // buf ready for all threads; s_out init; prev ph2 done

        // ---- Phase 1: per strip, all filters: conv -> +b -> square -> strip sum ----
        if (tid < NSTR) {
            const int s = tid;
            const float* xr0 = &s_x[buf][0][5 * s];   // window [5s .. 5s+20]
            const float* xr1 = &s_x[buf][1][5 * s];
            u64 xv[21];
            #pragma unroll
            for (int j = 0; j < 21; ++j) xv[j] = pack2(xr0[j], xr1[j]);  // LDS.32 x2, conflict-free

            for (int f = 0; f < NF; ++f) {
                const ulonglong2* wv = (const ulonglong2*)&s_w2[f * WSTR];
                const u64 b2 = s_b2[f];
                u64 c0 = b2, c1 = b2, c2 = b2, c3 = b2, c4 = b2;
                #pragma unroll
                for (int kp = 0; kp < 8; ++kp) {          // k = 2kp, 2kp+1
                    const ulonglong2 wpair = wv[kp];      // one LDS.128 -> two weights
                    const int k = 2 * kp;
                    c0 = ffma2(xv[k    ], wpair.x, c0);
                    c1 = ffma2(xv[k + 1], wpair.x, c1);
                    c2 = ffma2(xv[k + 2], wpair.x, c2);
                    c3 = ffma2(xv[k + 3], wpair.x, c3);
                    c4 = ffma2(xv[k + 4], wpair.x, c4);
                    c0 = ffma2(xv[k + 1], wpair.y, c0);
                    c1 = ffma2(xv[k + 2], wpair.y, c1);
                    c2 = ffma2(xv[k + 3], wpair.y, c2);
                    c3 = ffma2(xv[k + 4], wpair.y, c3);
                    c4 = ffma2(xv[k + 5], wpair.y, c4);
                }
                {
                    const u64 w16 = ((const u64*)wv)[16];  // k = 16
                    c0 = ffma2(xv[16], w16, c0);
                    c1 = ffma2(xv[17], w16, c1);
                    c2 = ffma2(xv[18], w16, c2);
                    c3 = ffma2(xv[19], w16, c3);
                    c4 = ffma2(xv[20], w16, c4);
                }
                u64 S = ffma2(c0, c0, 0ull);
                S = ffma2(c1, c1, S);
                S = ffma2(c2, c2, S);
                S = ffma2(c3, c3, S);
                S = ffma2(c4, c4, S);
                s_S2[f * NSTR + s] = S;
            }
        }
        __syncthreads();   // x reads + s_S2 writes complete

        // Prefetch pair p+2 into this buffer (safe: all x reads for buf are done)
        if (p + 2 < NPAIR) { PREFETCH(p + 2, buf); }
        else               { cp_commit(); }   // keep group count uniform

        // ---- Phase 2: packed sliding pool (15 strips/window, hop 3) -> log -> dot ----
        float part0 = 0.f, part1 = 0.f;
        for (int task = tid; task < NF * NTPG; task += THREADS) {   // 190 tasks
            int f = task / NTPG;
            int g = task - f * NTPG;            // covers tp = 4g .. 4g+3

            const u64* Sp = &s_S2[f * NSTR + 12 * g];
            u64 run2 = Sp[0];
            #pragma unroll
            for (int j = 1; j < 15; ++j) run2 = add2(run2, Sp[j]);

            const size_t fb = (size_t)f * NTP + 4 * g;
            const float4 lw0 = *(const float4*)&lin_w[(size_t)m0 * FEAT + fb];
            const float4 lw1 = *(const float4*)&lin_w[(size_t)(m0 + 1) * FEAT + fb];

            #pragma unroll
            for (int q = 0; q < 4; ++q) {
                float p0, p1; unpack2(run2, p0, p1);
                p0 = fmaxf(p0 * (1.0f / 75.0f), 1e-10f);
                p1 = fmaxf(p1 * (1.0f / 75.0f), 1e-10f);
                const float v0 = __logf(p0);
                const float v1 = __logf(p1);
                const float w0 = (q == 0) ? lw0.x : (q == 1) ? lw0.y : (q == 2) ? lw0.z : lw0.w;
                const float w1 = (q == 0) ? lw1.x : (q == 1) ? lw1.y : (q == 2) ? lw1.z : lw1.w;
                part0 = fmaf(v0, w0, part0);
                part1 = fmaf(v1, w1, part1);
                if (q < 3) {
                    u64 addv = add2(add2(Sp[15 + 3*q], Sp[16 + 3*q]), Sp[17 + 3*q]);
                    u64 subv = add2(add2(Sp[3*q], Sp[1 + 3*q]), Sp[2 + 3*q]);
                    run2 = sub2(add2(run2, addv), subv);
                }
            }
        }
        #pragma unroll
        for (int off = 16; off > 0; off >>= 1) {
            part0 += __shfl_down_sync(0xffffffffu, part0, off);
            part1 += __shfl_down_sync(0xffffffffu, part1, off);
        }
        if ((tid & 31) == 0) {
            atomicAdd(&s_out[0], part0);
            atomicAdd(&s_out[1], part1);
        }
        __syncthreads();

        if (tid < 2) out[row0 + tid] = s_out[tid] + lin_b[m0 + tid];
        // next iteration's leading __syncthreads orders s_out reuse
    }
    #undef PREFETCH
}

extern "C" void kernel_launch(void* const* d_in, const int* in_sizes, int n_in,
                              void* d_out, int out_size) {
    const float* x      = (const float*)d_in[0];
    const float* conv_w = (const float*)d_in[1];
    const float* conv_b = (const float*)d_in[2];
    const float* lin_w  = (const float*)d_in[3];
    const float* lin_b  = (const float*)d_in[4];
    float* out = (float*)d_out;

    const int n_pairs  = 256 * 64 / 2;           // 8192 row-pairs
    scorer_kernel<<<n_pairs / NPAIR, THREADS>>>(x, conv_w, conv_b, lin_w, lin_b, out);
}